// round 16
// baseline (speedup 1.0000x reference)
#include <cuda_runtime.h>
#include <cuda_fp16.h>
#include <math.h>
#include <stdint.h>

#define TT   4096
#define DIM  1024
#define HEADS 16
#define HD   64
#define MLPD 4096
#define NPERS 296   // 2 CTAs x 148 SMs

// ---------------- scratch (device globals; no allocation allowed) ------------
__device__ float  g_ada[6 * DIM];
__device__ __half g_h[TT * DIM];          // reused for h2
__device__ __half g_qkv[TT * 3 * DIM];
__device__ __half g_attn[TT * DIM];
__device__ float  g_x1[TT * DIM];
__device__ __half g_mlp[TT * MLPD];
__device__ __half g_wt[12 * 1024 * 1024]; // transposed fp16 weights

// ---------------- helpers -----------------------------------------------------
__device__ __forceinline__ void mma_f16(float* d, const uint32_t* a,
                                        uint32_t b0, uint32_t b1) {
    asm volatile(
        "mma.sync.aligned.m16n8k16.row.col.f32.f16.f16.f32 "
        "{%0,%1,%2,%3}, {%4,%5,%6,%7}, {%8,%9}, {%0,%1,%2,%3};"
        : "+f"(d[0]), "+f"(d[1]), "+f"(d[2]), "+f"(d[3])
        : "r"(a[0]), "r"(a[1]), "r"(a[2]), "r"(a[3]), "r"(b0), "r"(b1));
}
__device__ __forceinline__ void ldsm_x4(uint32_t addr, uint32_t* r) {
    asm volatile("ldmatrix.sync.aligned.m8n8.x4.shared.b16 {%0,%1,%2,%3}, [%4];"
                 : "=r"(r[0]), "=r"(r[1]), "=r"(r[2]), "=r"(r[3])
                 : "r"(addr) : "memory");
}
__device__ __forceinline__ void cp_async16(uint32_t dst, const void* src) {
    asm volatile("cp.async.cg.shared.global [%0], [%1], 16;"
                 :: "r"(dst), "l"(src));
}
__device__ __forceinline__ void cp_commit() {
    asm volatile("cp.async.commit_group;");
}
__device__ __forceinline__ void cp_wait1() {
    asm volatile("cp.async.wait_group 1;");
}
__device__ __forceinline__ uint32_t smem_u32(const void* p) {
    return (uint32_t)__cvta_generic_to_shared(p);
}
__device__ __forceinline__ float tanh_fast(float x) {
    float r;
    asm("tanh.approx.f32 %0, %1;" : "=f"(r) : "f"(x));
    return r;
}

// ---------------- ada = c @ w_ada + b_ada -----------------------------------
__global__ void ada_kernel(const float* __restrict__ c,
                           const float* __restrict__ w,
                           const float* __restrict__ b,
                           float* __restrict__ ada) {
    __shared__ float cs[DIM];
    int tid = threadIdx.x;
    for (int i = tid; i < DIM; i += 256) cs[i] = c[i];
    __syncthreads();
    int j = blockIdx.x * 256 + tid;
    float acc = b[j];
    for (int k = 0; k < DIM; k++)
        acc += cs[k] * w[(size_t)k * (6 * DIM) + j];
    ada[j] = acc;
}

// ---------------- weight convert + transpose: wt[n][k] = fp16(w[k][n]) -------
__global__ void wconv_kernel(const float* __restrict__ w,
                             __half* __restrict__ wt, int K, int N) {
    __shared__ float t[32][33];
    int n0 = blockIdx.x * 32, k0 = blockIdx.y * 32;
    int tx = threadIdx.x & 31, ty = threadIdx.x >> 5;   // 32 x 8
#pragma unroll
    for (int i = 0; i < 32; i += 8)
        t[ty + i][tx] = w[(size_t)(k0 + ty + i) * N + n0 + tx];
    __syncthreads();
#pragma unroll
    for (int i = 0; i < 32; i += 8)
        wt[(size_t)(n0 + ty + i) * K + k0 + tx] = __float2half_rn(t[tx][ty + i]);
}

// ---------------- LayerNorm + adaLN modulation (fp16 output) ------------------
__global__ void ln_mod_kernel(const float* __restrict__ x,
                              __half* __restrict__ out,
                              const float* __restrict__ w,
                              const float* __restrict__ b,
                              const float* __restrict__ ada,
                              int sh_off, int sc_off) {
    __shared__ float red[256];
    int t = blockIdx.x, tid = threadIdx.x;
    const float* xr = x + (size_t)t * DIM;
    float v[4];
    float sum = 0.f, sq = 0.f;
#pragma unroll
    for (int j = 0; j < 4; j++) {
        v[j] = xr[tid + 256 * j];
        sum += v[j];
        sq += v[j] * v[j];
    }
    red[tid] = sum; __syncthreads();
    for (int s = 128; s > 0; s >>= 1) { if (tid < s) red[tid] += red[tid + s]; __syncthreads(); }
    float mu = red[0] * (1.0f / DIM);
    __syncthreads();
    red[tid] = sq; __syncthreads();
    for (int s = 128; s > 0; s >>= 1) { if (tid < s) red[tid] += red[tid + s]; __syncthreads(); }
    float var = red[0] * (1.0f / DIM) - mu * mu;
    float rstd = rsqrtf(var + 1e-5f);
#pragma unroll
    for (int j = 0; j < 4; j++) {
        int d = tid + 256 * j;
        float hn = (v[j] - mu) * rstd * w[d] + b[d];
        out[(size_t)t * DIM + d] =
            __float2half_rn(hn * (1.f + ada[sc_off + d]) + ada[sh_off + d]);
    }
}

// ---------------- persistent fp16 GEMM: grid-stride tiles, 3-stage x k64 -----
// C = A[M,K] @ Bt[N,K]^T + epilogue. Grid = min(ntiles, NPERS); each CTA loops
// over tiles; the cp.async ring continues across tile boundaries (last two
// stages of tile t prefetch stages 0-1 of tile t+gridDim), hiding prologue and
// epilogue and smoothing wave tails.
// EPI 0: plain (fp16), 1: bias+GELU (fp16), 2: resid+gate (fp32),
// EPI 3: qkv with fused RoPE on q,k (bias=cos, gate=sin).
#define HTS 72
#define HTILE_BYTES (128 * HTS * 2)                 // 18432
#define GEMM_SMEM_BYTES (3 * 2 * HTILE_BYTES)       // 110592

template <int EPI>
__global__ __launch_bounds__(256, 2)
void tgemm_kernel(const __half* __restrict__ A, const __half* __restrict__ Bt,
                  void* __restrict__ Cv, int M, int N, int K,
                  const float* __restrict__ bias,
                  const float* __restrict__ gate,
                  const float* __restrict__ resid) {
    extern __shared__ float smem[];
    uint32_t sA = smem_u32(smem);
    uint32_t sB = sA + 3 * HTILE_BYTES;

    int tid = threadIdx.x;
    int lane = tid & 31;
    int warp = tid >> 5;
    int wm = warp >> 1;
    int wn = warp & 1;

    int ntM = M >> 7;
    int ntiles = ntM * (N >> 7);
    int nsteps = K >> 6;

    int fr_row = lane & 15;
    int fr_k8  = (lane >> 4) << 3;
    uint32_t a_off = (uint32_t)(((wm * 32 + fr_row) * HTS + fr_k8) * 2);
    uint32_t b_off = (uint32_t)(((wn * 64 + fr_row) * HTS + fr_k8) * 2);
    int g = lane >> 2, t4 = lane & 3;

    auto issue_tile = [&](const __half* Ap, const __half* Bp, int s, int bufi) {
        int k0 = s << 6;
#pragma unroll
        for (int i = 0; i < 4; i++) {
            int cid = tid + (i << 8);
            int row = cid >> 3, c = cid & 7;
            uint32_t dst = (uint32_t)(bufi * HTILE_BYTES + row * (HTS * 2) + c * 16);
            cp_async16(sA + dst, Ap + (size_t)row * K + k0 + c * 8);
            cp_async16(sB + dst, Bp + (size_t)row * K + k0 + c * 8);
        }
        cp_commit();
    };

    int tl = blockIdx.x;
    if (tl >= ntiles) return;
    const __half* Ab = A + (size_t)(tl % ntM) * 128 * K;
    const __half* Bb = Bt + (size_t)(tl / ntM) * 128 * K;
    issue_tile(Ab, Bb, 0, 0);
    issue_tile(Ab, Bb, 1, 1);

    int buf = 0, nbuf = 2;
    for (; tl < ntiles; tl += gridDim.x) {
        int by = tl % ntM, bx = tl / ntM;
        int tn = tl + gridDim.x;
        bool hn = tn < ntiles;
        const __half* An = hn ? A + (size_t)(tn % ntM) * 128 * K : A;
        const __half* Bn = hn ? Bt + (size_t)(tn / ntM) * 128 * K : Bt;

        float acc[2][8][4];
#pragma unroll
        for (int mi = 0; mi < 2; mi++)
#pragma unroll
            for (int ni = 0; ni < 8; ni++)
#pragma unroll
                for (int r = 0; r < 4; r++) acc[mi][ni][r] = 0.f;

        for (int s = 0; s < nsteps; s++) {
            cp_wait1();
            __syncthreads();

            if (s + 2 < nsteps) issue_tile(Ab, Bb, s + 2, nbuf);
            else if (hn)        issue_tile(An, Bn, s + 2 - nsteps, nbuf);
            else                cp_commit();

            uint32_t a_base = sA + (uint32_t)buf * HTILE_BYTES + a_off;
            uint32_t b_base = sB + (uint32_t)buf * HTILE_BYTES + b_off;
#pragma unroll
            for (int kd = 0; kd < 4; kd++) {
                uint32_t koff = (uint32_t)(kd * 32);
                uint32_t afr[2][4], bfr[4][4];
#pragma unroll
                for (int mi = 0; mi < 2; mi++)
                    ldsm_x4(a_base + (uint32_t)(mi * 16 * HTS * 2) + koff, afr[mi]);
#pragma unroll
                for (int nb2 = 0; nb2 < 4; nb2++)
                    ldsm_x4(b_base + (uint32_t)(nb2 * 16 * HTS * 2) + koff, bfr[nb2]);
#pragma unroll
                for (int nb2 = 0; nb2 < 4; nb2++)
#pragma unroll
                    for (int mi = 0; mi < 2; mi++) {
                        mma_f16(acc[mi][nb2 * 2 + 0], afr[mi], bfr[nb2][0], bfr[nb2][2]);
                        mma_f16(acc[mi][nb2 * 2 + 1], afr[mi], bfr[nb2][1], bfr[nb2][3]);
                    }
            }

            buf = (buf == 2) ? 0 : buf + 1;
            nbuf = (nbuf == 2) ? 0 : nbuf + 1;
        }

        // ---- epilogue for tile (bx, by); next tile's loads already in flight
        int nbase = bx * 128 + wn * 64;
        bool do_rope = (EPI == 3) && (nbase < 2 * DIM);
#pragma unroll
        for (int mi = 0; mi < 2; mi++) {
            int row0 = by * 128 + wm * 32 + mi * 16 + g;
#pragma unroll
            for (int half = 0; half < 2; half++) {
                int row = row0 + half * 8;
                if (EPI == 3) {
                    if (do_rope) {
                        const float* cb = bias + (size_t)row * 32;
                        const float* sb = gate + (size_t)row * 32;
#pragma unroll
                        for (int ni = 0; ni < 4; ni++) {
                            int d = ni * 8 + t4 * 2;
                            float x1a = acc[mi][ni][half * 2 + 0];
                            float x1b = acc[mi][ni][half * 2 + 1];
                            float x2a = acc[mi][ni + 4][half * 2 + 0];
                            float x2b = acc[mi][ni + 4][half * 2 + 1];
                            float c0 = cb[d], s0 = sb[d], c1 = cb[d + 1], s1 = sb[d + 1];
                            __half* cp = (__half*)Cv + (size_t)row * N + nbase + d;
                            *(__half2*)cp =
                                __floats2half2_rn(x1a * c0 - x2a * s0, x1b * c1 - x2b * s1);
                            *(__half2*)(cp + 32) =
                                __floats2half2_rn(x2a * c0 + x1a * s0, x2b * c1 + x1b * s1);
                        }
                    } else {
#pragma unroll
                        for (int ni = 0; ni < 8; ni++) {
                            int col = nbase + ni * 8 + t4 * 2;
                            *(__half2*)((__half*)Cv + (size_t)row * N + col) =
                                __floats2half2_rn(acc[mi][ni][half * 2 + 0],
                                                  acc[mi][ni][half * 2 + 1]);
                        }
                    }
                    continue;
                }
#pragma unroll
                for (int ni = 0; ni < 8; ni++) {
                    int col = nbase + ni * 8 + t4 * 2;
                    float v0 = acc[mi][ni][half * 2 + 0];
                    float v1 = acc[mi][ni][half * 2 + 1];
                    if (EPI == 0) {
                        *(__half2*)((__half*)Cv + (size_t)row * N + col) =
                            __floats2half2_rn(v0, v1);
                    } else if (EPI == 1) {
                        v0 += bias[col]; v1 += bias[col + 1];
                        float g0 = 0.5f * v0 * (1.f + tanh_fast(0.7978845608028654f * (v0 + 0.044715f * v0 * v0 * v0)));
                        float g1 = 0.5f * v1 * (1.f + tanh_fast(0.7978845608028654f * (v1 + 0.044715f * v1 * v1 * v1)));
                        *(__half2*)((__half*)Cv + (size_t)row * N + col) =
                            __floats2half2_rn(g0, g1);
                    } else {
                        if (bias) { v0 += bias[col]; v1 += bias[col + 1]; }
                        float2 r = *(const float2*)(resid + (size_t)row * N + col);
                        float* cp = (float*)Cv + (size_t)row * N + col;
                        *(float2*)cp = make_float2(r.x + gate[col] * v0,
                                                   r.y + gate[col + 1] * v1);
                    }
                }
            }
        }

        Ab = An; Bb = Bn;
    }
}

// ---------------- fp16 tensor-core flash attention (block-diagonal) -----------
#define QTS2 72
#define PTS  40
__global__ __launch_bounds__(128)
void attn_kernel(const __half* __restrict__ qkv,
                 const int* __restrict__ seq_idx,
                 __half* __restrict__ out) {
    __shared__ __half qs[64 * QTS2];
    __shared__ __half ks[32 * QTS2];
    __shared__ __half vt[64 * PTS];   // [d][key]
    __shared__ __half ps[64 * PTS];   // [m][key]
    __shared__ int sq[64];
    __shared__ int sk[32];
    __shared__ int range[2];

    int head = blockIdx.y;
    int q0 = blockIdx.x * 64;
    int tid = threadIdx.x;
    int lane = tid & 31;
    int warp = tid >> 5;
    int g = lane >> 2, t = lane & 3;

    int fr_row = lane & 15;
    int fr_k8  = (lane >> 4) << 3;

    uint32_t qs_sh = smem_u32(qs);
    uint32_t ks_sh = smem_u32(ks);
    uint32_t vt_sh = smem_u32(vt);
    uint32_t ps_sh = smem_u32(ps);

#pragma unroll
    for (int p = 0; p < 4; p++) {
        int idx = tid + p * 128;
        int r = idx >> 3, c8 = idx & 7;
        uint4 v = *(const uint4*)(qkv + (size_t)(q0 + r) * (3 * DIM) + head * HD + c8 * 8);
        *(uint4*)&qs[r * QTS2 + c8 * 8] = v;
    }
    if (tid < 64) sq[tid] = seq_idx[q0 + tid];
    if (tid == 0) {
        int slo = seq_idx[q0], shi = seq_idx[q0 + 63];
        int lo = 0, hi = TT;
        while (lo < hi) { int mid = (lo + hi) >> 1; if (seq_idx[mid] < slo) lo = mid + 1; else hi = mid; }
        range[0] = lo >> 5;
        lo = 0; hi = TT;
        while (lo < hi) { int mid = (lo + hi) >> 1; if (seq_idx[mid] <= shi) lo = mid + 1; else hi = mid; }
        range[1] = (lo - 1) >> 5;
    }
    __syncthreads();
    int kb_lo = range[0], kb_hi = range[1];
    int sqr0 = sq[warp * 16 + g], sqr1 = sq[warp * 16 + g + 8];

    float m0 = -1e30f, m1 = -1e30f, l0 = 0.f, l1 = 0.f;
    float oacc[8][4];
#pragma unroll
    for (int nt = 0; nt < 8; nt++)
#pragma unroll
        for (int r = 0; r < 4; r++) oacc[nt][r] = 0.f;

    for (int kb = kb_lo; kb <= kb_hi; kb++) {
        int k0 = kb * 32;
        if (tid < 32) sk[tid] = seq_idx[k0 + tid];
#pragma unroll
        for (int p = 0; p < 2; p++) {
            int idx = tid + p * 128;
            int key = idx >> 3, c8 = idx & 7;
            const __half* base = qkv + (size_t)(k0 + key) * (3 * DIM) + head * HD + c8 * 8;
            uint4 kv = *(const uint4*)(base + DIM);
            *(uint4*)&ks[key * QTS2 + c8 * 8] = kv;
            const __half* vb = base + 2 * DIM;
#pragma unroll
            for (int e = 0; e < 8; e++)
                vt[(c8 * 8 + e) * PTS + key] = vb[e];
        }
        __syncthreads();

        float sacc[4][4];
#pragma unroll
        for (int nt = 0; nt < 4; nt++)
#pragma unroll
            for (int r = 0; r < 4; r++) sacc[nt][r] = 0.f;
        uint32_t qa = qs_sh + (uint32_t)(((warp * 16 + fr_row) * QTS2 + fr_k8) * 2);
        uint32_t kbb = ks_sh + (uint32_t)((fr_row * QTS2 + fr_k8) * 2);
#pragma unroll
        for (int kd = 0; kd < 4; kd++) {
            uint32_t koff = (uint32_t)(kd * 32);
            uint32_t afr[4], bfr0[4], bfr1[4];
            ldsm_x4(qa + koff, afr);
            ldsm_x4(kbb + koff, bfr0);
            ldsm_x4(kbb + (uint32_t)(16 * QTS2 * 2) + koff, bfr1);
            mma_f16(sacc[0], afr, bfr0[0], bfr0[2]);
            mma_f16(sacc[1], afr, bfr0[1], bfr0[3]);
            mma_f16(sacc[2], afr, bfr1[0], bfr1[2]);
            mma_f16(sacc[3], afr, bfr1[1], bfr1[3]);
        }
#pragma unroll
        for (int nt = 0; nt < 4; nt++)
#pragma unroll
            for (int r = 0; r < 4; r++) sacc[nt][r] *= 0.125f;

        float p0v[8], p1v[8];
        {
            float mx0 = -1e30f, mx1 = -1e30f;
#pragma unroll
            for (int nt = 0; nt < 4; nt++) {
                int c0 = nt * 8 + 2 * t, c1 = c0 + 1;
                int s0 = sk[c0], s1 = sk[c1];
                if (sqr0 != s0) sacc[nt][0] = -1e30f;
                if (sqr0 != s1) sacc[nt][1] = -1e30f;
                if (sqr1 != s0) sacc[nt][2] = -1e30f;
                if (sqr1 != s1) sacc[nt][3] = -1e30f;
                mx0 = fmaxf(mx0, fmaxf(sacc[nt][0], sacc[nt][1]));
                mx1 = fmaxf(mx1, fmaxf(sacc[nt][2], sacc[nt][3]));
            }
#pragma unroll
            for (int o = 1; o <= 2; o <<= 1) {
                mx0 = fmaxf(mx0, __shfl_xor_sync(0xffffffffu, mx0, o));
                mx1 = fmaxf(mx1, __shfl_xor_sync(0xffffffffu, mx1, o));
            }
            float mn0 = fmaxf(m0, mx0), mn1 = fmaxf(m1, mx1);
            float sc0 = __expf(m0 - mn0), sc1 = __expf(m1 - mn1);
            float rs0 = 0.f, rs1 = 0.f;
#pragma unroll
            for (int nt = 0; nt < 4; nt++) {
                p0v[nt * 2 + 0] = __expf(sacc[nt][0] - mn0);
                p0v[nt * 2 + 1] = __expf(sacc[nt][1] - mn0);
                p1v[nt * 2 + 0] = __expf(sacc[nt][2] - mn1);
                p1v[nt * 2 + 1] = __expf(sacc[nt][3] - mn1);
                rs0 += p0v[nt * 2] + p0v[nt * 2 + 1];
                rs1 += p1v[nt * 2] + p1v[nt * 2 + 1];
            }
#pragma unroll
            for (int o = 1; o <= 2; o <<= 1) {
                rs0 += __shfl_xor_sync(0xffffffffu, rs0, o);
                rs1 += __shfl_xor_sync(0xffffffffu, rs1, o);
            }
            l0 = l0 * sc0 + rs0; m0 = mn0;
            l1 = l1 * sc1 + rs1; m1 = mn1;
#pragma unroll
            for (int nt = 0; nt < 8; nt++) {
                oacc[nt][0] *= sc0; oacc[nt][1] *= sc0;
                oacc[nt][2] *= sc1; oacc[nt][3] *= sc1;
            }
            int r0 = warp * 16 + g, r1 = r0 + 8;
#pragma unroll
            for (int nt = 0; nt < 4; nt++) {
                int c0 = nt * 8 + 2 * t;
                *(__half2*)&ps[r0 * PTS + c0] = __floats2half2_rn(p0v[nt * 2], p0v[nt * 2 + 1]);
                *(__half2*)&ps[r1 * PTS + c0] = __floats2half2_rn(p1v[nt * 2], p1v[nt * 2 + 1]);
            }
        }
        __syncwarp();

        uint32_t pa = ps_sh + (uint32_t)(((warp * 16 + fr_row) * PTS + fr_k8) * 2);
#pragma unroll
        for (int ks16 = 0; ks16 < 2; ks16++) {
            uint32_t koff = (uint32_t)(ks16 * 32);
            uint32_t pfr[4];
            ldsm_x4(pa + koff, pfr);
#pragma unroll
            for (int nb2 = 0; nb2 < 4; nb2++) {
                uint32_t vfr[4];
                ldsm_x4(vt_sh + (uint32_t)(((nb2 * 16 + fr_row) * PTS + fr_k8) * 2) + koff, vfr);
                mma_f16(oacc[nb2 * 2 + 0], pfr, vfr[0], vfr[2]);
                mma_f16(oacc[nb2 * 2 + 1], pfr, vfr[1], vfr[3]);
            }
        }
        __syncthreads();
    }

    float inv0 = 1.f / l0, inv1 = 1.f / l1;
    int r0 = q0 + warp * 16 + g, r1 = r0 + 8;
#pragma unroll
    for (int nt = 0; nt < 8; nt++) {
        int col = head * HD + nt * 8 + 2 * t;
        *(__half2*)(out + (size_t)r0 * DIM + col) =
            __floats2half2_rn(oacc[nt][0] * inv0, oacc[nt][1] * inv0);
        *(__half2*)(out + (size_t)r1 * DIM + col) =
            __floats2half2_rn(oacc[nt][2] * inv1, oacc[nt][3] * inv1);
    }
}

// ---------------- pre-main initialization -------------------------------------
static float  *p_ada, *p_x1;
static __half *p_h, *p_qkv, *p_attn, *p_mlp, *p_wt;

namespace {
struct DevInit {
    DevInit() {
        cudaGetSymbolAddress((void**)&p_ada,  g_ada);
        cudaGetSymbolAddress((void**)&p_h,    g_h);
        cudaGetSymbolAddress((void**)&p_qkv,  g_qkv);
        cudaGetSymbolAddress((void**)&p_attn, g_attn);
        cudaGetSymbolAddress((void**)&p_x1,   g_x1);
        cudaGetSymbolAddress((void**)&p_mlp,  g_mlp);
        cudaGetSymbolAddress((void**)&p_wt,   g_wt);
        cudaFuncSetAttribute(tgemm_kernel<0>, cudaFuncAttributeMaxDynamicSharedMemorySize, GEMM_SMEM_BYTES);
        cudaFuncSetAttribute(tgemm_kernel<1>, cudaFuncAttributeMaxDynamicSharedMemorySize, GEMM_SMEM_BYTES);
        cudaFuncSetAttribute(tgemm_kernel<2>, cudaFuncAttributeMaxDynamicSharedMemorySize, GEMM_SMEM_BYTES);
        cudaFuncSetAttribute(tgemm_kernel<3>, cudaFuncAttributeMaxDynamicSharedMemorySize, GEMM_SMEM_BYTES);
        // warm-launch every kernel (lazy arena allocs happen pre-checkpoint)
        ada_kernel<<<1, 256>>>(p_x1, (const float*)p_mlp, p_x1, p_ada);
        wconv_kernel<<<dim3(1, 1), 256>>>(p_x1, p_wt, 1024, 1024);
        ln_mod_kernel<<<1, 256>>>(p_x1, p_h, p_x1, p_x1, p_ada, 0, DIM);
        tgemm_kernel<0><<<1, 256, GEMM_SMEM_BYTES>>>(
            p_h, p_wt, p_qkv, 128, 128, 128, nullptr, nullptr, nullptr);
        tgemm_kernel<1><<<1, 256, GEMM_SMEM_BYTES>>>(
            p_h, p_wt, p_mlp, 128, 128, 128, p_x1, nullptr, nullptr);
        tgemm_kernel<2><<<1, 256, GEMM_SMEM_BYTES>>>(
            p_h, p_wt, p_x1, 128, 128, 128, p_x1, p_ada, p_x1);
        tgemm_kernel<3><<<1, 256, GEMM_SMEM_BYTES>>>(
            p_h, p_wt, p_qkv, 128, 128, 128, p_x1, p_x1, nullptr);
        attn_kernel<<<dim3(1, 1), 128>>>(p_qkv, (const int*)p_x1, p_attn);
        cudaDeviceSynchronize();
        cudaGetLastError();  // clear any sticky state
    }
};
DevInit g_devinit;
}  // namespace

static inline int pgrid(int ntiles) { return ntiles < NPERS ? ntiles : NPERS; }

// ---------------- host launcher ----------------------------------------------
extern "C" void kernel_launch(void* const* d_in, const int* in_sizes, int n_in,
                              void* d_out, int out_size) {
    const float* x      = (const float*)d_in[0];
    const float* c      = (const float*)d_in[1];
    const float* cosb   = (const float*)d_in[2];
    const float* sinb   = (const float*)d_in[3];
    const int*   seqidx = (const int*)d_in[4];
    const float* ln1_w  = (const float*)d_in[5];
    const float* ln1_b  = (const float*)d_in[6];
    const float* w_qkv  = (const float*)d_in[7];
    const float* w_out  = (const float*)d_in[8];
    const float* ln2_w  = (const float*)d_in[9];
    const float* ln2_b  = (const float*)d_in[10];
    const float* w_mlp1 = (const float*)d_in[11];
    const float* b_mlp1 = (const float*)d_in[12];
    const float* w_mlp2 = (const float*)d_in[13];
    const float* b_mlp2 = (const float*)d_in[14];
    const float* w_ada  = (const float*)d_in[15];
    const float* b_ada  = (const float*)d_in[16];
    float* out = (float*)d_out;

    __half* wt_qkv  = p_wt;
    __half* wt_out  = p_wt + 3 * 1024 * 1024;
    __half* wt_mlp1 = p_wt + 4 * 1024 * 1024;
    __half* wt_mlp2 = p_wt + 8 * 1024 * 1024;

    // 0. weight convert+transpose (fp16, [N][K])
    wconv_kernel<<<dim3(3 * DIM / 32, DIM / 32), 256>>>(w_qkv,  wt_qkv,  DIM, 3 * DIM);
    wconv_kernel<<<dim3(DIM / 32, DIM / 32), 256>>>(w_out,  wt_out,  DIM, DIM);
    wconv_kernel<<<dim3(MLPD / 32, DIM / 32), 256>>>(w_mlp1, wt_mlp1, DIM, MLPD);
    wconv_kernel<<<dim3(DIM / 32, MLPD / 32), 256>>>(w_mlp2, wt_mlp2, MLPD, DIM);
    // 1. ada modulation vector
    ada_kernel<<<6 * DIM / 256, 256>>>(c, w_ada, b_ada, p_ada);
    // 2. h = fp16(LN1(x) * (1+sc_msa) + sh_msa)
    ln_mod_kernel<<<TT, 256>>>(x, p_h, ln1_w, ln1_b, p_ada, 0, DIM);
    // 3. qkv = h @ w_qkv with fused RoPE on q,k (fp16 out)
    tgemm_kernel<3><<<pgrid(32 * 24), 256, GEMM_SMEM_BYTES>>>(
        p_h, wt_qkv, p_qkv, TT, 3 * DIM, DIM, cosb, sinb, nullptr);
    // 4. attention (fp16 tensor cores)
    attn_kernel<<<dim3(TT / 64, HEADS), 128>>>(p_qkv, seqidx, p_attn);
    // 5. x1 = x + g_msa * (attn @ w_out)   (fp32 out)
    tgemm_kernel<2><<<pgrid(32 * 8), 256, GEMM_SMEM_BYTES>>>(
        p_attn, wt_out, p_x1, TT, DIM, DIM, nullptr, p_ada + 2 * DIM, x);
    // 6. h2 = fp16(LN2(x1) * (1+sc_mlp) + sh_mlp)
    ln_mod_kernel<<<TT, 256>>>(p_x1, p_h, ln2_w, ln2_b, p_ada, 3 * DIM, 4 * DIM);
    // 7. mlp = fp16(gelu(h2 @ w_mlp1 + b_mlp1))
    tgemm_kernel<1><<<pgrid(32 * 32), 256, GEMM_SMEM_BYTES>>>(
        p_h, wt_mlp1, p_mlp, TT, MLPD, DIM, b_mlp1, nullptr, nullptr);
    // 8. out = x1 + g_mlp * (mlp @ w_mlp2 + b_mlp2)   (fp32 out)
    tgemm_kernel<2><<<pgrid(32 * 8), 256, GEMM_SMEM_BYTES>>>(
        p_mlp, wt_mlp2, out, TT, DIM, MLPD, b_mlp2, p_ada + 5 * DIM, p_x1);
}

// round 17
// speedup vs baseline: 1.0691x; 1.0691x over previous
#include <cuda_runtime.h>
#include <cuda_fp16.h>
#include <math.h>
#include <stdint.h>

#define TT   4096
#define DIM  1024
#define HEADS 16
#define HD   64
#define MLPD 4096

// ---------------- scratch (device globals; no allocation allowed) ------------
__device__ float  g_ada[6 * DIM];
__device__ __half g_h[TT * DIM];          // reused for h2
__device__ __half g_qkv[TT * 3 * DIM];
__device__ __half g_attn[TT * DIM];
__device__ float  g_x1[TT * DIM];
__device__ __half g_mlp[TT * MLPD];
__device__ __half g_wt[12 * 1024 * 1024]; // transposed fp16 weights

// ---------------- helpers -----------------------------------------------------
__device__ __forceinline__ void mma_f16(float* d, const uint32_t* a,
                                        uint32_t b0, uint32_t b1) {
    asm volatile(
        "mma.sync.aligned.m16n8k16.row.col.f32.f16.f16.f32 "
        "{%0,%1,%2,%3}, {%4,%5,%6,%7}, {%8,%9}, {%0,%1,%2,%3};"
        : "+f"(d[0]), "+f"(d[1]), "+f"(d[2]), "+f"(d[3])
        : "r"(a[0]), "r"(a[1]), "r"(a[2]), "r"(a[3]), "r"(b0), "r"(b1));
}
__device__ __forceinline__ void ldsm_x4(uint32_t addr, uint32_t* r) {
    asm volatile("ldmatrix.sync.aligned.m8n8.x4.shared.b16 {%0,%1,%2,%3}, [%4];"
                 : "=r"(r[0]), "=r"(r[1]), "=r"(r[2]), "=r"(r[3])
                 : "r"(addr) : "memory");
}
__device__ __forceinline__ void cp_async16(uint32_t dst, const void* src) {
    asm volatile("cp.async.cg.shared.global [%0], [%1], 16;"
                 :: "r"(dst), "l"(src));
}
__device__ __forceinline__ void cp_commit() {
    asm volatile("cp.async.commit_group;");
}
__device__ __forceinline__ void cp_wait1() {
    asm volatile("cp.async.wait_group 1;");
}
__device__ __forceinline__ uint32_t smem_u32(const void* p) {
    return (uint32_t)__cvta_generic_to_shared(p);
}
__device__ __forceinline__ float tanh_fast(float x) {
    float r;
    asm("tanh.approx.f32 %0, %1;" : "=f"(r) : "f"(x));
    return r;
}

// ---------------- ada = c @ w_ada + b_ada -----------------------------------
__global__ void ada_kernel(const float* __restrict__ c,
                           const float* __restrict__ w,
                           const float* __restrict__ b,
                           float* __restrict__ ada) {
    __shared__ float cs[DIM];
    int tid = threadIdx.x;
    for (int i = tid; i < DIM; i += 256) cs[i] = c[i];
    __syncthreads();
    int j = blockIdx.x * 256 + tid;
    float acc = b[j];
    for (int k = 0; k < DIM; k++)
        acc += cs[k] * w[(size_t)k * (6 * DIM) + j];
    ada[j] = acc;
}

// ---------------- weight convert + transpose: wt[n][k] = fp16(w[k][n]) -------
__global__ void wconv_kernel(const float* __restrict__ w,
                             __half* __restrict__ wt, int K, int N) {
    __shared__ float t[32][33];
    int n0 = blockIdx.x * 32, k0 = blockIdx.y * 32;
    int tx = threadIdx.x & 31, ty = threadIdx.x >> 5;   // 32 x 8
#pragma unroll
    for (int i = 0; i < 32; i += 8)
        t[ty + i][tx] = w[(size_t)(k0 + ty + i) * N + n0 + tx];
    __syncthreads();
#pragma unroll
    for (int i = 0; i < 32; i += 8)
        wt[(size_t)(n0 + ty + i) * K + k0 + tx] = __float2half_rn(t[tx][ty + i]);
}

// ---------------- LayerNorm + adaLN modulation (fp16 output) ------------------
__global__ void ln_mod_kernel(const float* __restrict__ x,
                              __half* __restrict__ out,
                              const float* __restrict__ w,
                              const float* __restrict__ b,
                              const float* __restrict__ ada,
                              int sh_off, int sc_off) {
    __shared__ float red[256];
    int t = blockIdx.x, tid = threadIdx.x;
    const float* xr = x + (size_t)t * DIM;
    float v[4];
    float sum = 0.f, sq = 0.f;
#pragma unroll
    for (int j = 0; j < 4; j++) {
        v[j] = xr[tid + 256 * j];
        sum += v[j];
        sq += v[j] * v[j];
    }
    red[tid] = sum; __syncthreads();
    for (int s = 128; s > 0; s >>= 1) { if (tid < s) red[tid] += red[tid + s]; __syncthreads(); }
    float mu = red[0] * (1.0f / DIM);
    __syncthreads();
    red[tid] = sq; __syncthreads();
    for (int s = 128; s > 0; s >>= 1) { if (tid < s) red[tid] += red[tid + s]; __syncthreads(); }
    float var = red[0] * (1.0f / DIM) - mu * mu;
    float rstd = rsqrtf(var + 1e-5f);
#pragma unroll
    for (int j = 0; j < 4; j++) {
        int d = tid + 256 * j;
        float hn = (v[j] - mu) * rstd * w[d] + b[d];
        out[(size_t)t * DIM + d] =
            __float2half_rn(hn * (1.f + ada[sc_off + d]) + ada[sh_off + d]);
    }
}

// ---------------- fp16 GEMM: cp.async + ldmatrix, 3-stage x k64 --------------
// C = A[M,K] @ Bt[N,K]^T + epilogue. A,Bt fp16; accum fp32.
// Tiles 128x128x64, 8 warps (4M x 2N), warp tile 32x64.
// Smem [row][k] stride 72 halves. One __syncthreads per k64 stage.
// EPI 0: plain (fp16), 1: bias+GELU (fp16), 2: resid+gate (fp32),
// EPI 3: qkv with fused RoPE on q,k columns (bias=cos, gate=sin).
#define HTS 72
#define HTILE_BYTES (128 * HTS * 2)                 // 18432
#define GEMM_SMEM_BYTES (3 * 2 * HTILE_BYTES)       // 110592

template <int EPI>
__global__ __launch_bounds__(256, 2)
void tgemm_kernel(const __half* __restrict__ A, const __half* __restrict__ Bt,
                  void* __restrict__ Cv, int M, int N, int K,
                  const float* __restrict__ bias,
                  const float* __restrict__ gate,
                  const float* __restrict__ resid) {
    extern __shared__ float smem[];
    uint32_t sA = smem_u32(smem);
    uint32_t sB = sA + 3 * HTILE_BYTES;

    int tid = threadIdx.x;
    int lane = tid & 31;
    int warp = tid >> 5;
    int wm = warp >> 1;
    int wn = warp & 1;
    int bx = blockIdx.x, by = blockIdx.y;

    const __half* Ab = A + (size_t)by * 128 * K;
    const __half* Bb = Bt + (size_t)bx * 128 * K;

    int fr_row = lane & 15;
    int fr_k8  = (lane >> 4) << 3;   // 0 or 8 halves
    uint32_t a_off = (uint32_t)(((wm * 32 + fr_row) * HTS + fr_k8) * 2);
    uint32_t b_off = (uint32_t)(((wn * 64 + fr_row) * HTS + fr_k8) * 2);

    float acc[2][8][4];
#pragma unroll
    for (int mi = 0; mi < 2; mi++)
#pragma unroll
        for (int ni = 0; ni < 8; ni++)
#pragma unroll
            for (int r = 0; r < 4; r++) acc[mi][ni][r] = 0.f;

    int nsteps = K >> 6;

    auto issue_tile = [&](int s, int buf) {
        int k0 = s << 6;
#pragma unroll
        for (int i = 0; i < 4; i++) {
            int cid = tid + (i << 8);
            int row = cid >> 3, c = cid & 7;
            uint32_t dst = (uint32_t)(buf * HTILE_BYTES + row * (HTS * 2) + c * 16);
            cp_async16(sA + dst, Ab + (size_t)row * K + k0 + c * 8);
            cp_async16(sB + dst, Bb + (size_t)row * K + k0 + c * 8);
        }
        cp_commit();
    };

    issue_tile(0, 0);
    if (nsteps > 1) issue_tile(1, 1); else cp_commit();

    int buf = 0, nbuf = 2;
    for (int s = 0; s < nsteps; s++) {
        cp_wait1();
        __syncthreads();

        if (s + 2 < nsteps) issue_tile(s + 2, nbuf);
        else cp_commit();

        uint32_t a_base = sA + (uint32_t)buf * HTILE_BYTES + a_off;
        uint32_t b_base = sB + (uint32_t)buf * HTILE_BYTES + b_off;
#pragma unroll
        for (int kd = 0; kd < 4; kd++) {
            uint32_t koff = (uint32_t)(kd * 32);
            uint32_t afr[2][4], bfr[4][4];
#pragma unroll
            for (int mi = 0; mi < 2; mi++)
                ldsm_x4(a_base + (uint32_t)(mi * 16 * HTS * 2) + koff, afr[mi]);
#pragma unroll
            for (int nb2 = 0; nb2 < 4; nb2++)
                ldsm_x4(b_base + (uint32_t)(nb2 * 16 * HTS * 2) + koff, bfr[nb2]);
#pragma unroll
            for (int nb2 = 0; nb2 < 4; nb2++)
#pragma unroll
                for (int mi = 0; mi < 2; mi++) {
                    mma_f16(acc[mi][nb2 * 2 + 0], afr[mi], bfr[nb2][0], bfr[nb2][2]);
                    mma_f16(acc[mi][nb2 * 2 + 1], afr[mi], bfr[nb2][1], bfr[nb2][3]);
                }
        }

        buf = (buf == 2) ? 0 : buf + 1;
        nbuf = (nbuf == 2) ? 0 : nbuf + 1;
    }

    // epilogue
    int g = lane >> 2, t = lane & 3;
    int nbase = bx * 128 + wn * 64;              // warp's 64-wide head block
    bool do_rope = (EPI == 3) && (nbase < 2 * DIM);   // q or k block (warp-uniform)
#pragma unroll
    for (int mi = 0; mi < 2; mi++) {
        int row0 = by * 128 + wm * 32 + mi * 16 + g;
#pragma unroll
        for (int half = 0; half < 2; half++) {
            int row = row0 + half * 8;
            if (EPI == 3) {
                if (do_rope) {
                    const float* cb = bias + (size_t)row * 32;
                    const float* sb = gate + (size_t)row * 32;
#pragma unroll
                    for (int ni = 0; ni < 4; ni++) {
                        int d = ni * 8 + t * 2;
                        float x1a = acc[mi][ni][half * 2 + 0];
                        float x1b = acc[mi][ni][half * 2 + 1];
                        float x2a = acc[mi][ni + 4][half * 2 + 0];
                        float x2b = acc[mi][ni + 4][half * 2 + 1];
                        float c0 = cb[d], s0 = sb[d], c1 = cb[d + 1], s1 = sb[d + 1];
                        __half* cp = (__half*)Cv + (size_t)row * N + nbase + d;
                        *(__half2*)cp =
                            __floats2half2_rn(x1a * c0 - x2a * s0, x1b * c1 - x2b * s1);
                        *(__half2*)(cp + 32) =
                            __floats2half2_rn(x2a * c0 + x1a * s0, x2b * c1 + x1b * s1);
                    }
                } else {
#pragma unroll
                    for (int ni = 0; ni < 8; ni++) {
                        int col = nbase + ni * 8 + t * 2;
                        *(__half2*)((__half*)Cv + (size_t)row * N + col) =
                            __floats2half2_rn(acc[mi][ni][half * 2 + 0],
                                              acc[mi][ni][half * 2 + 1]);
                    }
                }
                continue;
            }
#pragma unroll
            for (int ni = 0; ni < 8; ni++) {
                int col = nbase + ni * 8 + t * 2;
                float v0 = acc[mi][ni][half * 2 + 0];
                float v1 = acc[mi][ni][half * 2 + 1];
                if (EPI == 0) {
                    *(__half2*)((__half*)Cv + (size_t)row * N + col) =
                        __floats2half2_rn(v0, v1);
                } else if (EPI == 1) {
                    v0 += bias[col]; v1 += bias[col + 1];
                    float g0 = 0.5f * v0 * (1.f + tanh_fast(0.7978845608028654f * (v0 + 0.044715f * v0 * v0 * v0)));
                    float g1 = 0.5f * v1 * (1.f + tanh_fast(0.7978845608028654f * (v1 + 0.044715f * v1 * v1 * v1)));
                    *(__half2*)((__half*)Cv + (size_t)row * N + col) =
                        __floats2half2_rn(g0, g1);
                } else {
                    if (bias) { v0 += bias[col]; v1 += bias[col + 1]; }
                    float2 r = *(const float2*)(resid + (size_t)row * N + col);
                    float* cp = (float*)Cv + (size_t)row * N + col;
                    *(float2*)cp = make_float2(r.x + gate[col] * v0,
                                               r.y + gate[col + 1] * v1);
                }
            }
        }
    }
}

// ---------------- fp16 tensor-core flash attention (block-diagonal) -----------
// CTA: 256 threads (8 warps), BM=128 queries x BN=32 keys, HD=64.
// Each warp owns 16 query rows; per-warp S/softmax/PV identical to the BM=64
// version. K/V tile loads + barriers amortize over 2x the queries.
#define QTS2 72
#define PTS  40
__global__ __launch_bounds__(256)
void attn_kernel(const __half* __restrict__ qkv,
                 const int* __restrict__ seq_idx,
                 __half* __restrict__ out) {
    __shared__ __half qs[128 * QTS2];
    __shared__ __half ks[32 * QTS2];
    __shared__ __half vt[64 * PTS];    // [d][key]
    __shared__ __half ps[128 * PTS];   // [m][key]
    __shared__ int sq[128];
    __shared__ int sk[32];
    __shared__ int range[2];

    int head = blockIdx.y;
    int q0 = blockIdx.x * 128;
    int tid = threadIdx.x;
    int lane = tid & 31;
    int warp = tid >> 5;               // 0..7, rows warp*16 .. +15
    int g = lane >> 2, t = lane & 3;

    int fr_row = lane & 15;
    int fr_k8  = (lane >> 4) << 3;

    uint32_t qs_sh = smem_u32(qs);
    uint32_t ks_sh = smem_u32(ks);
    uint32_t vt_sh = smem_u32(vt);
    uint32_t ps_sh = smem_u32(ps);

    // load Q: 128 rows x 8 chunks = 1024 x 16B chunks over 256 threads
#pragma unroll
    for (int p = 0; p < 4; p++) {
        int idx = tid + p * 256;
        int r = idx >> 3, c8 = idx & 7;
        uint4 v = *(const uint4*)(qkv + (size_t)(q0 + r) * (3 * DIM) + head * HD + c8 * 8);
        *(uint4*)&qs[r * QTS2 + c8 * 8] = v;
    }
    if (tid < 128) sq[tid] = seq_idx[q0 + tid];
    if (tid == 0) {
        int slo = seq_idx[q0], shi = seq_idx[q0 + 127];
        int lo = 0, hi = TT;
        while (lo < hi) { int mid = (lo + hi) >> 1; if (seq_idx[mid] < slo) lo = mid + 1; else hi = mid; }
        range[0] = lo >> 5;
        lo = 0; hi = TT;
        while (lo < hi) { int mid = (lo + hi) >> 1; if (seq_idx[mid] <= shi) lo = mid + 1; else hi = mid; }
        range[1] = (lo - 1) >> 5;
    }
    __syncthreads();
    int kb_lo = range[0], kb_hi = range[1];
    int sqr0 = sq[warp * 16 + g], sqr1 = sq[warp * 16 + g + 8];

    float m0 = -1e30f, m1 = -1e30f, l0 = 0.f, l1 = 0.f;
    float oacc[8][4];
#pragma unroll
    for (int nt = 0; nt < 8; nt++)
#pragma unroll
        for (int r = 0; r < 4; r++) oacc[nt][r] = 0.f;

    for (int kb = kb_lo; kb <= kb_hi; kb++) {
        int k0 = kb * 32;
        if (tid < 32) sk[tid] = seq_idx[k0 + tid];
        // K: 32 rows x 8 chunks = 256 tasks (one pass); V transposed
        {
            int key = tid >> 3, c8 = tid & 7;
            const __half* base = qkv + (size_t)(k0 + key) * (3 * DIM) + head * HD + c8 * 8;
            uint4 kv = *(const uint4*)(base + DIM);
            *(uint4*)&ks[key * QTS2 + c8 * 8] = kv;
            uint4 vv = *(const uint4*)(base + 2 * DIM);
            const __half* ve = (const __half*)&vv;
#pragma unroll
            for (int e = 0; e < 8; e++)
                vt[(c8 * 8 + e) * PTS + key] = ve[e];
        }
        __syncthreads();

        // S = Q K^T  (4 k16-steps over HD=64)
        float sacc[4][4];
#pragma unroll
        for (int nt = 0; nt < 4; nt++)
#pragma unroll
            for (int r = 0; r < 4; r++) sacc[nt][r] = 0.f;
        uint32_t qa = qs_sh + (uint32_t)(((warp * 16 + fr_row) * QTS2 + fr_k8) * 2);
        uint32_t kbb = ks_sh + (uint32_t)((fr_row * QTS2 + fr_k8) * 2);
#pragma unroll
        for (int kd = 0; kd < 4; kd++) {
            uint32_t koff = (uint32_t)(kd * 32);
            uint32_t afr[4], bfr0[4], bfr1[4];
            ldsm_x4(qa + koff, afr);
            ldsm_x4(kbb + koff, bfr0);
            ldsm_x4(kbb + (uint32_t)(16 * QTS2 * 2) + koff, bfr1);
            mma_f16(sacc[0], afr, bfr0[0], bfr0[2]);
            mma_f16(sacc[1], afr, bfr0[1], bfr0[3]);
            mma_f16(sacc[2], afr, bfr1[0], bfr1[2]);
            mma_f16(sacc[3], afr, bfr1[1], bfr1[3]);
        }
#pragma unroll
        for (int nt = 0; nt < 4; nt++)
#pragma unroll
            for (int r = 0; r < 4; r++) sacc[nt][r] *= 0.125f;

        // mask + online softmax; write P (fp16) to smem
        float p0v[8], p1v[8];
        {
            float mx0 = -1e30f, mx1 = -1e30f;
#pragma unroll
            for (int nt = 0; nt < 4; nt++) {
                int c0 = nt * 8 + 2 * t, c1 = c0 + 1;
                int s0 = sk[c0], s1 = sk[c1];
                if (sqr0 != s0) sacc[nt][0] = -1e30f;
                if (sqr0 != s1) sacc[nt][1] = -1e30f;
                if (sqr1 != s0) sacc[nt][2] = -1e30f;
                if (sqr1 != s1) sacc[nt][3] = -1e30f;
                mx0 = fmaxf(mx0, fmaxf(sacc[nt][0], sacc[nt][1]));
                mx1 = fmaxf(mx1, fmaxf(sacc[nt][2], sacc[nt][3]));
            }
#pragma unroll
            for (int o = 1; o <= 2; o <<= 1) {
                mx0 = fmaxf(mx0, __shfl_xor_sync(0xffffffffu, mx0, o));
                mx1 = fmaxf(mx1, __shfl_xor_sync(0xffffffffu, mx1, o));
            }
            float mn0 = fmaxf(m0, mx0), mn1 = fmaxf(m1, mx1);
            float sc0 = __expf(m0 - mn0), sc1 = __expf(m1 - mn1);
            float rs0 = 0.f, rs1 = 0.f;
#pragma unroll
            for (int nt = 0; nt < 4; nt++) {
                p0v[nt * 2 + 0] = __expf(sacc[nt][0] - mn0);
                p0v[nt * 2 + 1] = __expf(sacc[nt][1] - mn0);
                p1v[nt * 2 + 0] = __expf(sacc[nt][2] - mn1);
                p1v[nt * 2 + 1] = __expf(sacc[nt][3] - mn1);
                rs0 += p0v[nt * 2] + p0v[nt * 2 + 1];
                rs1 += p1v[nt * 2] + p1v[nt * 2 + 1];
            }
#pragma unroll
            for (int o = 1; o <= 2; o <<= 1) {
                rs0 += __shfl_xor_sync(0xffffffffu, rs0, o);
                rs1 += __shfl_xor_sync(0xffffffffu, rs1, o);
            }
            l0 = l0 * sc0 + rs0; m0 = mn0;
            l1 = l1 * sc1 + rs1; m1 = mn1;
#pragma unroll
            for (int nt = 0; nt < 8; nt++) {
                oacc[nt][0] *= sc0; oacc[nt][1] *= sc0;
                oacc[nt][2] *= sc1; oacc[nt][3] *= sc1;
            }
            int r0 = warp * 16 + g, r1 = r0 + 8;
#pragma unroll
            for (int nt = 0; nt < 4; nt++) {
                int c0 = nt * 8 + 2 * t;
                *(__half2*)&ps[r0 * PTS + c0] = __floats2half2_rn(p0v[nt * 2], p0v[nt * 2 + 1]);
                *(__half2*)&ps[r1 * PTS + c0] = __floats2half2_rn(p1v[nt * 2], p1v[nt * 2 + 1]);
            }
        }
        __syncwarp();   // ps rows of this warp complete (read only by same warp)

        // O += P V  (2 k16-steps over 32 keys)
        uint32_t pa = ps_sh + (uint32_t)(((warp * 16 + fr_row) * PTS + fr_k8) * 2);
#pragma unroll
        for (int ks16 = 0; ks16 < 2; ks16++) {
            uint32_t koff = (uint32_t)(ks16 * 32);
            uint32_t pfr[4];
            ldsm_x4(pa + koff, pfr);
#pragma unroll
            for (int nb2 = 0; nb2 < 4; nb2++) {
                uint32_t vfr[4];
                ldsm_x4(vt_sh + (uint32_t)(((nb2 * 16 + fr_row) * PTS + fr_k8) * 2) + koff, vfr);
                mma_f16(oacc[nb2 * 2 + 0], pfr, vfr[0], vfr[2]);
                mma_f16(oacc[nb2 * 2 + 1], pfr, vfr[1], vfr[3]);
            }
        }
        __syncthreads();
    }

    float inv0 = 1.f / l0, inv1 = 1.f / l1;
    int r0 = q0 + warp * 16 + g, r1 = r0 + 8;
#pragma unroll
    for (int nt = 0; nt < 8; nt++) {
        int col = head * HD + nt * 8 + 2 * t;
        *(__half2*)(out + (size_t)r0 * DIM + col) =
            __floats2half2_rn(oacc[nt][0] * inv0, oacc[nt][1] * inv0);
        *(__half2*)(out + (size_t)r1 * DIM + col) =
            __floats2half2_rn(oacc[nt][2] * inv1, oacc[nt][3] * inv1);
    }
}

// ---------------- pre-main initialization -------------------------------------
static float  *p_ada, *p_x1;
static __half *p_h, *p_qkv, *p_attn, *p_mlp, *p_wt;

namespace {
struct DevInit {
    DevInit() {
        cudaGetSymbolAddress((void**)&p_ada,  g_ada);
        cudaGetSymbolAddress((void**)&p_h,    g_h);
        cudaGetSymbolAddress((void**)&p_qkv,  g_qkv);
        cudaGetSymbolAddress((void**)&p_attn, g_attn);
        cudaGetSymbolAddress((void**)&p_x1,   g_x1);
        cudaGetSymbolAddress((void**)&p_mlp,  g_mlp);
        cudaGetSymbolAddress((void**)&p_wt,   g_wt);
        cudaFuncSetAttribute(tgemm_kernel<0>, cudaFuncAttributeMaxDynamicSharedMemorySize, GEMM_SMEM_BYTES);
        cudaFuncSetAttribute(tgemm_kernel<1>, cudaFuncAttributeMaxDynamicSharedMemorySize, GEMM_SMEM_BYTES);
        cudaFuncSetAttribute(tgemm_kernel<2>, cudaFuncAttributeMaxDynamicSharedMemorySize, GEMM_SMEM_BYTES);
        cudaFuncSetAttribute(tgemm_kernel<3>, cudaFuncAttributeMaxDynamicSharedMemorySize, GEMM_SMEM_BYTES);
        // warm-launch every kernel (lazy arena allocs happen pre-checkpoint)
        ada_kernel<<<1, 256>>>(p_x1, (const float*)p_mlp, p_x1, p_ada);
        wconv_kernel<<<dim3(1, 1), 256>>>(p_x1, p_wt, 1024, 1024);
        ln_mod_kernel<<<1, 256>>>(p_x1, p_h, p_x1, p_x1, p_ada, 0, DIM);
        tgemm_kernel<0><<<dim3(1, 1), 256, GEMM_SMEM_BYTES>>>(
            p_h, p_wt, p_qkv, 128, 128, 128, nullptr, nullptr, nullptr);
        tgemm_kernel<1><<<dim3(1, 1), 256, GEMM_SMEM_BYTES>>>(
            p_h, p_wt, p_mlp, 128, 128, 128, p_x1, nullptr, nullptr);
        tgemm_kernel<2><<<dim3(1, 1), 256, GEMM_SMEM_BYTES>>>(
            p_h, p_wt, p_x1, 128, 128, 128, p_x1, p_ada, p_x1);
        tgemm_kernel<3><<<dim3(1, 1), 256, GEMM_SMEM_BYTES>>>(
            p_h, p_wt, p_qkv, 128, 128, 128, p_x1, p_x1, nullptr);
        attn_kernel<<<dim3(1, 1), 256>>>(p_qkv, (const int*)p_x1, p_attn);
        cudaDeviceSynchronize();
        cudaGetLastError();  // clear any sticky state
    }
};
DevInit g_devinit;
}  // namespace

// ---------------- host launcher ----------------------------------------------
extern "C" void kernel_launch(void* const* d_in, const int* in_sizes, int n_in,
                              void* d_out, int out_size) {
    const float* x      = (const float*)d_in[0];
    const float* c      = (const float*)d_in[1];
    const float* cosb   = (const float*)d_in[2];
    const float* sinb   = (const float*)d_in[3];
    const int*   seqidx = (const int*)d_in[4];
    const float* ln1_w  = (const float*)d_in[5];
    const float* ln1_b  = (const float*)d_in[6];
    const float* w_qkv  = (const float*)d_in[7];
    const float* w_out  = (const float*)d_in[8];
    const float* ln2_w  = (const float*)d_in[9];
    const float* ln2_b  = (const float*)d_in[10];
    const float* w_mlp1 = (const float*)d_in[11];
    const float* b_mlp1 = (const float*)d_in[12];
    const float* w_mlp2 = (const float*)d_in[13];
    const float* b_mlp2 = (const float*)d_in[14];
    const float* w_ada  = (const float*)d_in[15];
    const float* b_ada  = (const float*)d_in[16];
    float* out = (float*)d_out;

    __half* wt_qkv  = p_wt;
    __half* wt_out  = p_wt + 3 * 1024 * 1024;
    __half* wt_mlp1 = p_wt + 4 * 1024 * 1024;
    __half* wt_mlp2 = p_wt + 8 * 1024 * 1024;

    // 0. weight convert+transpose (fp16, [N][K])
    wconv_kernel<<<dim3(3 * DIM / 32, DIM / 32), 256>>>(w_qkv,  wt_qkv,  DIM, 3 * DIM);
    wconv_kernel<<<dim3(DIM / 32, DIM / 32), 256>>>(w_out,  wt_out,  DIM, DIM);
    wconv_kernel<<<dim3(MLPD / 32, DIM / 32), 256>>>(w_mlp1, wt_mlp1, DIM, MLPD);
    wconv_kernel<<<dim3(DIM / 32, MLPD / 32), 256>>>(w_mlp2, wt_mlp2, MLPD, DIM);
    // 1. ada modulation vector
    ada_kernel<<<6 * DIM / 256, 256>>>(c, w_ada, b_ada, p_ada);
    // 2. h = fp16(LN1(x) * (1+sc_msa) + sh_msa)
    ln_mod_kernel<<<TT, 256>>>(x, p_h, ln1_w, ln1_b, p_ada, 0, DIM);
    // 3. qkv = h @ w_qkv with fused RoPE on q,k (fp16 out)
    tgemm_kernel<3><<<dim3(3 * DIM / 128, TT / 128), 256, GEMM_SMEM_BYTES>>>(
        p_h, wt_qkv, p_qkv, TT, 3 * DIM, DIM, cosb, sinb, nullptr);
    // 4. attention (fp16 tensor cores, BM=128)
    attn_kernel<<<dim3(TT / 128, HEADS), 256>>>(p_qkv, seqidx, p_attn);
    // 5. x1 = x + g_msa * (attn @ w_out)   (fp32 out)
    tgemm_kernel<2><<<dim3(DIM / 128, TT / 128), 256, GEMM_SMEM_BYTES>>>(
        p_attn, wt_out, p_x1, TT, DIM, DIM, nullptr, p_ada + 2 * DIM, x);
    // 6. h2 = fp16(LN2(x1) * (1+sc_mlp) + sh_mlp)
    ln_mod_kernel<<<TT, 256>>>(p_x1, p_h, ln2_w, ln2_b, p_ada, 3 * DIM, 4 * DIM);
    // 7. mlp = fp16(gelu(h2 @ w_mlp1 + b_mlp1))
    tgemm_kernel<1><<<dim3(MLPD / 128, TT / 128), 256, GEMM_SMEM_BYTES>>>(
        p_h, wt_mlp1, p_mlp, TT, MLPD, DIM, b_mlp1, nullptr, nullptr);
    // 8. out = x1 + g_mlp * (mlp @ w_mlp2 + b_mlp2)   (fp32 out)
    tgemm_kernel<2><<<dim3(DIM / 128, TT / 128), 256, GEMM_SMEM_BYTES>>>(
        p_mlp, wt_mlp2, out, TT, DIM, MLPD, b_mlp2, p_ada + 5 * DIM, p_x1);
}